// round 17
// baseline (speedup 1.0000x reference)
#include <cuda_runtime.h>
#include <stdint.h>

// CubeSpherePadding2D, p=1: [16,64,6,96,96] f32 -> [16,64,6,98,98] f32.
// Pure gather of the original input (reference's 24 sequential edge writes
// resolved analytically; rel_err==0 verified rounds 1-16).
//
// Round-16b restructure: TWO CTAs per slice (top 50 / bottom 48 output rows).
// smem 38.4 -> 19.6KB per CTA -> 8 CTAs/SM at NT=256 = 2048 threads (100%
// theoretical occupancy), 8 TMA bulk stores in flight per SM, and the
// single-warp store-drain tail per CTA halves. Same proven pipeline:
// batched aligned LDG.128 -> shifted scalar STS -> one cp.async.bulk store.
//
// Sub-block alignment: top = 50*98*4 = 19,600 B, bottom = 48*98*4 = 18,816 B;
// both 16-divisible, and the bottom offset 19,600 is 16-aligned.

#define H 96
#define W 96
#define OH 98
#define OW 98
#define FACE (H * W)        // 9216
#define OFACE (OH * OW)     // 9604
#define NSLICES 6144        // 16*64*6
#define NT 256

__device__ __forceinline__ int src_off(int g, int y, int x) {
    return g * FACE + y * W + x;
}

// Source offset within the slice's 6-face block for a border output cell
// (f, r, c). Returns -1 for the zero corners (faces 0-3). Verified exact.
__device__ __forceinline__ int edge_src_offset(int f, int r, int c) {
    bool rin = (unsigned)(r - 1) < 96u;
    bool cin = (unsigned)(c - 1) < 96u;

    if (rin && cin) {
        return src_off(f, r - 1, c - 1);
    }
    if (cin) {                              // top/bottom row, non-corner
        bool top = (r == 0);
        switch (f) {
            case 0: return top ? src_off(4, 95, c - 1)   : src_off(5, 0, c - 1);
            case 1: return top ? src_off(4, 96 - c, 95)  : src_off(5, c - 1, 95);
            case 2: return top ? src_off(4, 0, 96 - c)   : src_off(5, 95, 96 - c);
            case 3: return top ? src_off(4, c - 1, 0)    : src_off(5, 96 - c, 0);
            case 4: return top ? src_off(2, 0, 96 - c)   : src_off(0, 0, c - 1);
            default:return top ? src_off(0, 95, c - 1)   : src_off(2, 95, 96 - c);
        }
    }
    if (rin) {                              // left/right column, non-corner
        bool right = (c == 97);
        switch (f) {
            case 0: return right ? src_off(1, r - 1, 0)  : src_off(3, r - 1, 95);
            case 1: return right ? src_off(2, r - 1, 0)  : src_off(0, r - 1, 95);
            case 2: return right ? src_off(3, r - 1, 0)  : src_off(1, r - 1, 95);
            case 3: return right ? src_off(0, r - 1, 0)  : src_off(2, r - 1, 95);
            case 4: return right ? src_off(1, 0, 96 - r) : src_off(3, 0, r - 1);
            default:return right ? src_off(1, 95, r - 1) : src_off(3, 95, 96 - r);
        }
    }
    // corners: faces 0-3 read still-zero padding (reference assignment order);
    // faces 4,5 resolve depth-2 to original data.
    if (f == 4) {
        if (r == 0) return (c == 0) ? src_off(3, 0, 0)   : src_off(1, 0, 95);
        else        return (c == 0) ? src_off(3, 0, 95)  : src_off(1, 0, 0);
    }
    if (f == 5) {
        if (r == 0) return (c == 0) ? src_off(3, 95, 95) : src_off(1, 95, 0);
        else        return (c == 0) ? src_off(3, 95, 0)  : src_off(1, 95, 95);
    }
    return -1;
}

__global__ void __launch_bounds__(NT)
cube_pad_half_kernel(const float* __restrict__ in,
                     float* __restrict__ out) {
    __shared__ __align__(16) float tile[50 * OW];   // 19,600 B (max of halves)

    const int blk  = blockIdx.x;
    const int s    = blk >> 1;                      // slice 0..6143
    const int half = blk & 1;                       // 0: rows 0..49, 1: 50..97
    const int tid  = threadIdx.x;
    const int f    = s % 6;
    const float* __restrict__ B0 = in + (size_t)(s - f) * FACE;

    const int hr0      = half ? 50 : 0;             // first output row of block
    const int nrows    = half ? 48 : 50;
    const int ri_start = half ? 49 : 0;             // first input row needed
    const int n4       = half ? (47 * 24) : (49 * 24);  // interior float4s
    const int rloc_off = half ? 0 : 1;              // tile row of 1st interior

    // Phase 1a: interior — aligned LDG.128, scalar STS shifted (+?,+1).
    const float4* __restrict__ in4 = reinterpret_cast<const float4*>(
        in + (size_t)s * FACE + (size_t)ri_start * W);
    for (int i = tid; i < n4; i += NT) {            // <=1176 -> <=5 iters
        float4 v = __ldg(in4 + i);
        int row = i / (W / 4);
        int c4  = i - row * (W / 4);
        int b   = (row + rloc_off) * OW + c4 * 4 + 1;
        tile[b]     = v.x;
        tile[b + 1] = v.y;
        tile[b + 2] = v.z;
        tile[b + 3] = v.w;
    }

    // Phase 1b: border cells of this half.
    // half 0: out row 0 (98) + cols c in {0,97} for r 1..49  (49+49) = 196
    // half 1: out row 97 (98) + cols c in {0,97} for r 50..96 (47+47) = 192
    const int nedge = half ? 192 : 196;
    for (int e = tid; e < nedge; e += NT) {
        int r, c;
        if (!half) {
            if (e < 98)       { r = 0;            c = e;  }
            else if (e < 147) { r = 1 + (e - 98); c = 0;  }
            else              { r = 1 + (e - 147); c = 97; }
        } else {
            if (e < 98)       { r = 97;            c = e;  }
            else if (e < 145) { r = 50 + (e - 98); c = 0;  }
            else              { r = 50 + (e - 145); c = 97; }
        }
        int off = edge_src_offset(f, r, c);
        tile[(r - hr0) * OW + c] = (off >= 0) ? __ldg(B0 + off) : 0.0f;
    }

    __syncthreads();

    // Phase 2: one TMA 1D bulk store of this half (19,600 / 18,816 B).
    if (tid == 0) {
        asm volatile("fence.proxy.async.shared::cta;" ::: "memory");

        uint32_t saddr;
        asm("{ .reg .u64 t; cvta.to.shared.u64 t, %1; cvt.u32.u64 %0, t; }"
            : "=r"(saddr) : "l"((const void*)tile));
        const float* gdst = out + (size_t)s * OFACE + (size_t)hr0 * OW;
        int nbytes = nrows * OW * 4;

        asm volatile(
            "cp.async.bulk.global.shared::cta.bulk_group [%0], [%1], %2;"
            :: "l"(gdst), "r"(saddr), "r"(nbytes)
            : "memory");
        asm volatile("cp.async.bulk.commit_group;" ::: "memory");
        asm volatile("cp.async.bulk.wait_group 0;" ::: "memory");
    }
}

extern "C" void kernel_launch(void* const* d_in, const int* in_sizes, int n_in,
                              void* d_out, int out_size) {
    const float* in = (const float*)d_in[0];
    float* out = (float*)d_out;

    cube_pad_half_kernel<<<NSLICES * 2, NT>>>(in, out);
}